// round 10
// baseline (speedup 1.0000x reference)
#include <cuda_runtime.h>
#include <cstdint>

#define NN 64
#define NMAT 4096
#define GRID_P 760             // 5 blocks x 152 SMs: exactly one resident wave
#define VAPPS 4                // + rowsum init = 5 applications total
#define RP 68                  // smem row pitch (words): bank-staggered rows

__device__ float g_acc[NN];
__device__ unsigned int g_ticket;

typedef unsigned long long u64;

__device__ __forceinline__ u64 ffma2(u64 a, u64 b, u64 c) {
    u64 d;
    asm("fma.rn.f32x2 %0, %1, %2, %3;" : "=l"(d) : "l"(a), "l"(b), "l"(c));
    return d;
}
__device__ __forceinline__ u64 fadd2(u64 a, u64 b) {
    u64 d;
    asm("add.rn.f32x2 %0, %1, %2;" : "=l"(d) : "l"(a), "l"(b));
    return d;
}
__device__ __forceinline__ void cp16(uint32_t dst, const void* src) {
    asm volatile("cp.async.cg.shared.global [%0], [%1], 16;" :: "r"(dst), "l"(src));
}
__device__ __forceinline__ u64 pack(float lo, float hi) {
    float2 f = make_float2(lo, hi);
    return *reinterpret_cast<u64*>(&f);
}

// Stream one 16KB matrix into a pitched smem tile (coalesced gmem, conflict-
// free smem: bank 4*((r+j) mod 8) with r fixed per phase, j consecutive).
__device__ __forceinline__ void issue_tile(float* bufp, const float* M, int t) {
    uint32_t b32 = (uint32_t)__cvta_generic_to_shared(bufp);
    const float4* src = reinterpret_cast<const float4*>(M);
#pragma unroll
    for (int i = 0; i < 4; ++i) {
        const int c = i * 256 + t;
        const int r = c >> 4, j = c & 15;
        cp16(b32 + (uint32_t)(r * RP + j * 4) * 4u, src + c);
    }
}

// 256 threads: k = t&63 (row), q = t>>6 (quarter; uniform per warp).
// Per matvec: FFMA2 from regs -> partial STS -> ONE barrier -> every thread
// rebuilds its v-window from the 4 partial rows via uniform broadcast LDS.
// Persistent: block processes matrices bid, bid+760, ... with a cp.async
// double buffer carried across the loop (one commit group per iteration).
__global__ __launch_bounds__(256, 5)
void power_kernel(const float* __restrict__ x,
                  const float* __restrict__ wt,
                  const float* __restrict__ rc,
                  float* __restrict__ out)
{
    const int t = threadIdx.x;
    const int k = t & 63;
    const int q = t >> 6;

    __shared__ __align__(16) float buf[2][NN * RP];
    __shared__ __align__(16) float part[4 * RP];
    __shared__ int is_last;

    const int m0 = (int)blockIdx.x;
    if (m0 < NMAT) issue_tile(buf[0], rc + (size_t)m0 * NN * NN, t);
    asm volatile("cp.async.commit_group;" ::: "memory");
    if (m0 + GRID_P < NMAT)
        issue_tile(buf[1], rc + (size_t)(m0 + GRID_P) * NN * NN, t);
    asm volatile("cp.async.commit_group;" ::: "memory");

#pragma unroll 1
    for (int i = 0, m = m0; m < NMAT; ++i, m += GRID_P) {
        const int s = m >> 6;
        asm volatile("cp.async.wait_group 1;" ::: "memory");
        __syncthreads();   // buf[i&1] ready; prior epilogue part-reads done

        const float mss = __ldg(rc + (size_t)m * NN * NN + s * NN + s);
        const float xw  = __ldg(x + m) * __ldg(wt + m);

        // Row quarter -> regs (words [16q,16q+16) of pitched row k).
        u64 row[8];
        {
            const float* bp = &buf[i & 1][k * RP + 16 * q];
#pragma unroll
            for (int j = 0; j < 4; ++j) {
                float4 f = *reinterpret_cast<const float4*>(bp + 4 * j);
                row[2 * j]     = pack(f.x, f.y);
                row[2 * j + 1] = pack(f.z, f.w);
            }
        }

        // Application 0: v = M*ones (scale irrelevant: output uses v[n]/v[s]).
        {
            u64 s0 = fadd2(fadd2(row[0], row[1]), fadd2(row[2], row[3]));
            u64 s1 = fadd2(fadd2(row[4], row[5]), fadd2(row[6], row[7]));
            u64 ss = fadd2(s0, s1);
            float2 f = *reinterpret_cast<float2*>(&ss);
            part[q * RP + k] = f.x + f.y;
        }
        __syncthreads();   // rows consumed by all + partials visible

        // Prefetch matrix m+2*GRID_P into the freed buffer (or empty group).
        if (m + 2 * GRID_P < NMAT)
            issue_tile(buf[i & 1], rc + (size_t)(m + 2 * GRID_P) * NN * NN, t);
        asm volatile("cp.async.commit_group;" ::: "memory");

        // v-window [16q,16q+16) = sum of the 4 partial rows (uniform LDS).
        u64 vw[8];
#pragma unroll
        for (int j = 0; j < 4; ++j) {
            float4 f = *reinterpret_cast<const float4*>(&part[16 * q + 4 * j]);
            vw[2 * j]     = pack(f.x, f.y);
            vw[2 * j + 1] = pack(f.z, f.w);
        }
#pragma unroll
        for (int qq = 1; qq < 4; ++qq)
#pragma unroll
            for (int j = 0; j < 4; ++j) {
                float4 f = *reinterpret_cast<const float4*>(
                    &part[qq * RP + 16 * q + 4 * j]);
                vw[2 * j]     = fadd2(vw[2 * j],     pack(f.x, f.y));
                vw[2 * j + 1] = fadd2(vw[2 * j + 1], pack(f.z, f.w));
            }

#pragma unroll
        for (int it = 0; it < VAPPS; ++it) {
            u64 a0 = 0, a1 = 0, a2 = 0, a3 = 0;
#pragma unroll
            for (int j = 0; j < 4; ++j) {
                if (j & 1) { a2 = ffma2(row[2*j], vw[2*j], a2);
                             a3 = ffma2(row[2*j+1], vw[2*j+1], a3); }
                else       { a0 = ffma2(row[2*j], vw[2*j], a0);
                             a1 = ffma2(row[2*j+1], vw[2*j+1], a1); }
            }
            u64 ss = fadd2(fadd2(a0, a2), fadd2(a1, a3));
            float2 f = *reinterpret_cast<float2*>(&ss);
            part[q * RP + k] = f.x + f.y;
            __syncthreads();                    // ONE barrier per matvec

            if (it < VAPPS - 1) {               // rebuild window (uniform LDS)
#pragma unroll
                for (int j = 0; j < 4; ++j) {
                    float4 f0 = *reinterpret_cast<const float4*>(
                        &part[16 * q + 4 * j]);
                    vw[2 * j]     = pack(f0.x, f0.y);
                    vw[2 * j + 1] = pack(f0.z, f0.w);
                }
#pragma unroll
                for (int qq = 1; qq < 4; ++qq)
#pragma unroll
                    for (int j = 0; j < 4; ++j) {
                        float4 f = *reinterpret_cast<const float4*>(
                            &part[qq * RP + 16 * q + 4 * j]);
                        vw[2 * j]     = fadd2(vw[2 * j],     pack(f.x, f.y));
                        vw[2 * j + 1] = fadd2(vw[2 * j + 1], pack(f.z, f.w));
                    }
            }
        }

        // Epilogue: q==0 lanes (64 threads) emit the atomics.
        if (q == 0) {
            const float vk = part[k] + part[RP + k]
                           + part[2 * RP + k] + part[3 * RP + k];
            const float vs = part[s] + part[RP + s]
                           + part[2 * RP + s] + part[3 * RP + s];
            atomicAdd(&g_acc[k], xw * mss / vs * vk);
        }
    }

    // Last block drains g_acc -> out and resets scratch (graph-replay safe).
    __threadfence();
    if (t == 0)
        is_last = (atomicAdd(&g_ticket, 1u) == (unsigned)(GRID_P - 1));
    __syncthreads();
    if (is_last) {
        if (t < NN) { out[t] = g_acc[t]; g_acc[t] = 0.0f; }
        if (t == 0) g_ticket = 0u;
    }
}

extern "C" void kernel_launch(void* const* d_in, const int* in_sizes, int n_in,
                              void* d_out, int out_size)
{
    // inputs: x, weights_t, weights_r (unused), r_zeros (all-zero), r_const
    const float* x  = (const float*)d_in[0];
    const float* wt = (const float*)d_in[1];
    const float* rc = (const float*)d_in[4];

    static bool carveout_set = false;
    if (!carveout_set) {
        cudaFuncSetAttribute(power_kernel,
                             cudaFuncAttributePreferredSharedMemoryCarveout, 100);
        carveout_set = true;
    }
    power_kernel<<<GRID_P, 256>>>(x, wt, rc, (float*)d_out);
}